// round 3
// baseline (speedup 1.0000x reference)
#include <cuda_runtime.h>
#include <cuda_bf16.h>
#include <cstdint>

// Problem constants (match reference)
#define NU    100000
#define NI    50000
#define NN    150000            // NU + NI
#define K     64
#define K2    32                // float2 per row (fp32) / uint32 per row (bf16x2)
#define FEAT  1024
#define NE    3000000
#define BATCH 16384
#define NBLK_SCAN 147           // ceil(150000/1024)

// ---------------- scratch (static device allocations; no cudaMalloc) --------
__device__ int      g_deg[NN];
__device__ int      g_fill[NN];          // running fill pointer (init = rowptr)
__device__ float    g_dinv[NN];
__device__ int      g_rowptr[NN + 1];
__device__ int      g_bsum[256];
__device__ int      g_boff[256];
__device__ int      g_col[2 * NE];       // 24 MB
__device__ float2   g_acc[NN * K2];      // 38.4 MB fp32 accumulator
__device__ uint32_t g_yA[NN * K2];       // 19.2 MB bf16x2
__device__ uint32_t g_yB[NN * K2];       // 19.2 MB bf16x2
__device__ float    g_proj[BATCH * K];   // 4 MB

// ---------------- kernels ---------------------------------------------------

__global__ void k_zero_counters() {
    int i = blockIdx.x * blockDim.x + threadIdx.x;
    if (i < NN) g_deg[i] = 0;
}

__global__ void k_count(const int* __restrict__ ue, const int* __restrict__ ie) {
    int e = blockIdx.x * blockDim.x + threadIdx.x;
    if (e >= NE) return;
    atomicAdd(&g_deg[ue[e]], 1);
    atomicAdd(&g_deg[NU + ie[e]], 1);
}

__global__ void k_dinv() {
    int i = blockIdx.x * blockDim.x + threadIdx.x;
    if (i >= NN) return;
    int d = g_deg[i];
    g_dinv[i] = (d > 0) ? rsqrtf((float)d) : 0.0f;
}

// Block-level exclusive scan of degrees (Hillis-Steele on 1024 elems)
__global__ void k_scanA() {
    __shared__ int sh[1024];
    int idx = blockIdx.x * 1024 + threadIdx.x;
    int v = (idx < NN) ? g_deg[idx] : 0;
    sh[threadIdx.x] = v;
    __syncthreads();
    for (int off = 1; off < 1024; off <<= 1) {
        int t = (threadIdx.x >= off) ? sh[threadIdx.x - off] : 0;
        __syncthreads();
        sh[threadIdx.x] += t;
        __syncthreads();
    }
    if (idx < NN) g_rowptr[idx] = sh[threadIdx.x] - v;  // exclusive
    if (threadIdx.x == 1023) g_bsum[blockIdx.x] = sh[1023];
}

__global__ void k_scanB() {
    if (threadIdx.x == 0) {
        int run = 0;
        for (int b = 0; b < NBLK_SCAN; b++) { int v = g_bsum[b]; g_boff[b] = run; run += v; }
        g_rowptr[NN] = run;
    }
}

__global__ void k_scanC() {
    int idx = blockIdx.x * blockDim.x + threadIdx.x;
    if (idx < NN) {
        int r = g_rowptr[idx] + g_boff[idx >> 10];
        g_rowptr[idx] = r;
        g_fill[idx] = r;     // fill pointer starts at row begin
    }
}

// Single atomic per edge endpoint: g_fill IS the running write cursor.
__global__ void k_fill(const int* __restrict__ ue, const int* __restrict__ ie) {
    int e = blockIdx.x * blockDim.x + threadIdx.x;
    if (e >= NE) return;
    int u = ue[e], it = NU + ie[e];
    int p = atomicAdd(&g_fill[u], 1);
    g_col[p] = it;
    int q = atomicAdd(&g_fill[it], 1);
    g_col[q] = u;
}

// acc = x0 (fp32) ; yA = bf16(dinv * x0)
__global__ void k_init(const float2* __restrict__ Gu, const float2* __restrict__ Gi) {
    int idx = blockIdx.x * blockDim.x + threadIdx.x;
    if (idx >= NN * K2) return;
    int n = idx >> 5;
    int c = idx & 31;
    float2 x0 = (n < NU) ? Gu[(size_t)n * K2 + c] : Gi[(size_t)(n - NU) * K2 + c];
    g_acc[idx] = x0;
    float dv = g_dinv[n];
    __nv_bfloat162 y = __float22bfloat162_rn(make_float2(x0.x * dv, x0.y * dv));
    g_yA[idx] = *reinterpret_cast<uint32_t*>(&y);
}

// One warp per node: x_next = dinv[d] * sum_{s in N(d)} y_in[s]  (y in bf16)
// acc += x_next (fp32) ; y_out = bf16(dinv[d] * x_next)
// flip==0: yin=g_yA, yout=g_yB.  flip==1: yin=g_yB, yout=g_yA.
__global__ void k_prop(int flip) {
    const uint32_t* __restrict__ yin = flip ? (const uint32_t*)g_yB : (const uint32_t*)g_yA;
    uint32_t* __restrict__ yout      = flip ? g_yA : g_yB;
    int w = (blockIdx.x * blockDim.x + threadIdx.x) >> 5;
    int lane = threadIdx.x & 31;
    if (w >= NN) return;
    int beg = g_rowptr[w], end = g_rowptr[w + 1];
    float sx = 0.f, sy = 0.f;
    int j = beg;
    for (; j + 8 <= end; j += 8) {
        uint32_t v[8];
        #pragma unroll
        for (int t = 0; t < 8; t++) {
            int c = g_col[j + t];
            v[t] = yin[(size_t)c * K2 + lane];
        }
        #pragma unroll
        for (int t = 0; t < 8; t++) {
            float2 f = __bfloat1622float2(*reinterpret_cast<__nv_bfloat162*>(&v[t]));
            sx += f.x; sy += f.y;
        }
    }
    for (; j < end; j++) {
        uint32_t v = yin[(size_t)g_col[j] * K2 + lane];
        float2 f = __bfloat1622float2(*reinterpret_cast<__nv_bfloat162*>(&v));
        sx += f.x; sy += f.y;
    }
    float dv = g_dinv[w];
    float xx = sx * dv, xy = sy * dv;
    size_t o = (size_t)w * K2 + lane;
    float2 ac = g_acc[o];
    ac.x += xx; ac.y += xy;
    g_acc[o] = ac;
    __nv_bfloat162 y = __float22bfloat162_rn(make_float2(xx * dv, xy * dv));
    yout[o] = *reinterpret_cast<uint32_t*>(&y);
}

// proj[b][k] = sum_f F[items[b]][f] * W[k][f] + bias[k]
// 64x64 output tile per block, BK=64, 256 threads (16x16), 4x4 micro-tile.
__global__ void k_gemm(const float* __restrict__ F, const float* __restrict__ W,
                       const float* __restrict__ bias, const int* __restrict__ items) {
    __shared__ float As[64][65];
    __shared__ float Bs[64][65];
    __shared__ int   its[64];
    int bm0 = blockIdx.x * 64;
    int tid = threadIdx.x;
    int tx = tid & 15, ty = tid >> 4;
    if (tid < 64) its[tid] = items[bm0 + tid];
    __syncthreads();
    float acc[4][4] = {};
    for (int f0 = 0; f0 < FEAT; f0 += 64) {
        #pragma unroll
        for (int i = 0; i < 16; i++) {
            int idx = tid + i * 256;
            int r = idx >> 6, c = idx & 63;
            As[r][c] = F[(size_t)its[r] * FEAT + f0 + c];
            Bs[c][r] = W[(size_t)r * FEAT + f0 + c];  // Bs[f][k]
        }
        __syncthreads();
        #pragma unroll
        for (int ff = 0; ff < 64; ff++) {
            float a[4], b[4];
            #pragma unroll
            for (int m = 0; m < 4; m++) a[m] = As[ty * 4 + m][ff];
            #pragma unroll
            for (int n = 0; n < 4; n++) b[n] = Bs[ff][tx * 4 + n];
            #pragma unroll
            for (int m = 0; m < 4; m++)
                #pragma unroll
                for (int n = 0; n < 4; n++)
                    acc[m][n] = fmaf(a[m], b[n], acc[m][n]);
        }
        __syncthreads();
    }
    #pragma unroll
    for (int m = 0; m < 4; m++)
        #pragma unroll
        for (int n = 0; n < 4; n++)
            g_proj[(size_t)(bm0 + ty * 4 + m) * K + tx * 4 + n] = acc[m][n] + bias[tx * 4 + n];
}

// One warp per batch element: out = dot(acc_u, acc_i)/16 + dot(Tu_u, proj_b)/max(||proj_b||,1e-12)
__global__ void k_final(const int* __restrict__ users, const int* __restrict__ items,
                        const float2* __restrict__ Tu, float* __restrict__ out) {
    int b = (blockIdx.x * blockDim.x + threadIdx.x) >> 5;
    int lane = threadIdx.x & 31;
    if (b >= BATCH) return;
    int u = users[b], it = items[b];
    float2 gu = g_acc[(size_t)u * K2 + lane];
    float2 gi = g_acc[(size_t)(NU + it) * K2 + lane];
    float d1 = gu.x * gi.x + gu.y * gi.y;
    float2 tu = Tu[(size_t)u * K2 + lane];
    const float2* pr2 = (const float2*)g_proj;
    float2 pr = pr2[(size_t)b * K2 + lane];
    float d2 = tu.x * pr.x + tu.y * pr.y;
    float ss = pr.x * pr.x + pr.y * pr.y;
    #pragma unroll
    for (int off = 16; off; off >>= 1) {
        d1 += __shfl_xor_sync(0xFFFFFFFFu, d1, off);
        d2 += __shfl_xor_sync(0xFFFFFFFFu, d2, off);
        ss += __shfl_xor_sync(0xFFFFFFFFu, ss, off);
    }
    if (lane == 0) {
        float nrm = sqrtf(ss);
        float den = fmaxf(nrm, 1e-12f);
        out[b] = d1 * (1.0f / 16.0f) + d2 / den;
    }
}

// ---------------- launch -----------------------------------------------------

extern "C" void kernel_launch(void* const* d_in, const int* in_sizes, int n_in,
                              void* d_out, int out_size) {
    const float* Gu     = (const float*)d_in[0];
    const float* Gi     = (const float*)d_in[1];
    const float* Tu     = (const float*)d_in[2];
    const float* F      = (const float*)d_in[3];
    const float* proj_w = (const float*)d_in[4];
    const float* proj_b = (const float*)d_in[5];
    const int*   ue     = (const int*)d_in[6];
    const int*   ie     = (const int*)d_in[7];
    const int*   users  = (const int*)d_in[8];
    const int*   items  = (const int*)d_in[9];
    float* out = (float*)d_out;

    k_zero_counters<<<(NN + 255) / 256, 256>>>();
    k_count<<<(NE + 255) / 256, 256>>>(ue, ie);
    k_dinv<<<(NN + 255) / 256, 256>>>();
    k_scanA<<<NBLK_SCAN, 1024>>>();
    k_scanB<<<1, 32>>>();
    k_scanC<<<(NN + 255) / 256, 256>>>();
    k_fill<<<(NE + 255) / 256, 256>>>(ue, ie);
    k_init<<<(NN * K2 + 255) / 256, 256>>>((const float2*)Gu, (const float2*)Gi);

    // 3 LightGCN layers: one warp per node, 8 warps per block
    const int PROP_BLOCKS = NN / 8;  // 150000/8 = 18750
    k_prop<<<PROP_BLOCKS, 256>>>(0);  // yA -> yB
    k_prop<<<PROP_BLOCKS, 256>>>(1);  // yB -> yA
    k_prop<<<PROP_BLOCKS, 256>>>(0);  // yA -> yB

    k_gemm<<<BATCH / 64, 256>>>(F, proj_w, proj_b, items);
    k_final<<<(BATCH * 32 + 255) / 256, 256>>>(users, items, (const float2*)Tu, out);
}

// round 4
// speedup vs baseline: 1.4337x; 1.4337x over previous
#include <cuda_runtime.h>
#include <cstdint>

// Problem constants (match reference)
#define NU    100000
#define NI    50000
#define NN    150000            // NU + NI
#define K     64
#define K4    16                // float4 per node row
#define FEAT  1024
#define NE    3000000
#define BATCH 16384
#define NBLK_SCAN 147           // ceil(150000/1024)

// ---------------- scratch (static device allocations; no cudaMalloc) --------
__device__ int    g_deg[NN];
__device__ int    g_fill[NN];            // running fill cursor (init = rowptr)
__device__ float  g_dinv[NN];
__device__ int    g_rowptr[NN + 1];
__device__ int    g_bsum[256];
__device__ int    g_boff[256];
__device__ int    g_col[2 * NE];         // 24 MB
__device__ float4 g_acc[NN * K4];        // 38.4 MB fp32 accumulator
__device__ float4 g_yA[NN * K4];         // 38.4 MB
__device__ float4 g_yB[NN * K4];         // 38.4 MB
__device__ float  g_proj[BATCH * K];     // 4 MB

// ---------------- kernels ---------------------------------------------------

__global__ void k_zero_counters() {
    int i = blockIdx.x * blockDim.x + threadIdx.x;
    if (i < NN) g_deg[i] = 0;
}

__global__ void k_count(const int* __restrict__ ue, const int* __restrict__ ie) {
    int e = blockIdx.x * blockDim.x + threadIdx.x;
    if (e >= NE) return;
    atomicAdd(&g_deg[ue[e]], 1);
    atomicAdd(&g_deg[NU + ie[e]], 1);
}

__global__ void k_dinv() {
    int i = blockIdx.x * blockDim.x + threadIdx.x;
    if (i >= NN) return;
    int d = g_deg[i];
    g_dinv[i] = (d > 0) ? rsqrtf((float)d) : 0.0f;
}

// Block-level exclusive scan of degrees (Hillis-Steele on 1024 elems)
__global__ void k_scanA() {
    __shared__ int sh[1024];
    int idx = blockIdx.x * 1024 + threadIdx.x;
    int v = (idx < NN) ? g_deg[idx] : 0;
    sh[threadIdx.x] = v;
    __syncthreads();
    for (int off = 1; off < 1024; off <<= 1) {
        int t = (threadIdx.x >= off) ? sh[threadIdx.x - off] : 0;
        __syncthreads();
        sh[threadIdx.x] += t;
        __syncthreads();
    }
    if (idx < NN) g_rowptr[idx] = sh[threadIdx.x] - v;  // exclusive
    if (threadIdx.x == 1023) g_bsum[blockIdx.x] = sh[1023];
}

__global__ void k_scanB() {
    if (threadIdx.x == 0) {
        int run = 0;
        for (int b = 0; b < NBLK_SCAN; b++) { int v = g_bsum[b]; g_boff[b] = run; run += v; }
        g_rowptr[NN] = run;
    }
}

__global__ void k_scanC() {
    int idx = blockIdx.x * blockDim.x + threadIdx.x;
    if (idx < NN) {
        int r = g_rowptr[idx] + g_boff[idx >> 10];
        g_rowptr[idx] = r;
        g_fill[idx] = r;   // fill cursor starts at row begin
    }
}

// Single atomic per edge endpoint: g_fill IS the running write cursor.
__global__ void k_fill(const int* __restrict__ ue, const int* __restrict__ ie) {
    int e = blockIdx.x * blockDim.x + threadIdx.x;
    if (e >= NE) return;
    int u = ue[e], it = NU + ie[e];
    int p = atomicAdd(&g_fill[u], 1);
    g_col[p] = it;
    int q = atomicAdd(&g_fill[it], 1);
    g_col[q] = u;
}

// acc = x0 ; yA = dinv * x0   (float4 lanes, 16 per node row)
__global__ void k_init(const float4* __restrict__ Gu, const float4* __restrict__ Gi) {
    int idx = blockIdx.x * blockDim.x + threadIdx.x;
    if (idx >= NN * K4) return;
    int n = idx >> 4;
    int c = idx & 15;
    float4 x0 = (n < NU) ? Gu[(size_t)n * K4 + c] : Gi[(size_t)(n - NU) * K4 + c];
    g_acc[idx] = x0;
    float dv = g_dinv[n];
    g_yA[idx] = make_float4(x0.x * dv, x0.y * dv, x0.z * dv, x0.w * dv);
}

// One HALF-WARP (16 lanes, float4 each) per node.
// x_next = dinv[d] * sum_{s in N(d)} y_in[s];  acc += x_next;  y_out = dinv[d]*x_next
__global__ void k_prop(int flip) {
    const float4* __restrict__ yin = flip ? (const float4*)g_yB : (const float4*)g_yA;
    float4* __restrict__ yout      = flip ? g_yA : g_yB;
    int hw   = (blockIdx.x * blockDim.x + threadIdx.x) >> 4;  // half-warp id = node
    int lane = threadIdx.x & 15;
    if (hw >= NN) return;
    int beg = g_rowptr[hw], end = g_rowptr[hw + 1];
    float sx = 0.f, sy = 0.f, sz = 0.f, sw = 0.f;
    int j = beg;
    for (; j + 4 <= end; j += 4) {
        int c0 = g_col[j], c1 = g_col[j + 1], c2 = g_col[j + 2], c3 = g_col[j + 3];
        float4 a0 = yin[(size_t)c0 * K4 + lane];
        float4 a1 = yin[(size_t)c1 * K4 + lane];
        float4 a2 = yin[(size_t)c2 * K4 + lane];
        float4 a3 = yin[(size_t)c3 * K4 + lane];
        sx += (a0.x + a1.x) + (a2.x + a3.x);
        sy += (a0.y + a1.y) + (a2.y + a3.y);
        sz += (a0.z + a1.z) + (a2.z + a3.z);
        sw += (a0.w + a1.w) + (a2.w + a3.w);
    }
    for (; j < end; j++) {
        float4 a = yin[(size_t)g_col[j] * K4 + lane];
        sx += a.x; sy += a.y; sz += a.z; sw += a.w;
    }
    float dv = g_dinv[hw];
    float xx = sx * dv, xy = sy * dv, xz = sz * dv, xw = sw * dv;
    size_t o = (size_t)hw * K4 + lane;
    float4 ac = g_acc[o];
    ac.x += xx; ac.y += xy; ac.z += xz; ac.w += xw;
    g_acc[o] = ac;
    yout[o] = make_float4(xx * dv, xy * dv, xz * dv, xw * dv);
}

// proj[b][k] = sum_f F[items[b]][f] * W[k][f] + bias[k]
// 64x64 output tile per block, BK=64, 256 threads (16x16), 4x4 micro-tile.
__global__ void k_gemm(const float* __restrict__ F, const float* __restrict__ W,
                       const float* __restrict__ bias, const int* __restrict__ items) {
    __shared__ float As[64][65];
    __shared__ float Bs[64][65];
    __shared__ int   its[64];
    int bm0 = blockIdx.x * 64;
    int tid = threadIdx.x;
    int tx = tid & 15, ty = tid >> 4;
    if (tid < 64) its[tid] = items[bm0 + tid];
    __syncthreads();
    float acc[4][4] = {};
    for (int f0 = 0; f0 < FEAT; f0 += 64) {
        #pragma unroll
        for (int i = 0; i < 16; i++) {
            int idx = tid + i * 256;
            int r = idx >> 6, c = idx & 63;
            As[r][c] = F[(size_t)its[r] * FEAT + f0 + c];
            Bs[c][r] = W[(size_t)r * FEAT + f0 + c];  // Bs[f][k]
        }
        __syncthreads();
        #pragma unroll
        for (int ff = 0; ff < 64; ff++) {
            float a[4], b[4];
            #pragma unroll
            for (int m = 0; m < 4; m++) a[m] = As[ty * 4 + m][ff];
            #pragma unroll
            for (int n = 0; n < 4; n++) b[n] = Bs[ff][tx * 4 + n];
            #pragma unroll
            for (int m = 0; m < 4; m++)
                #pragma unroll
                for (int n = 0; n < 4; n++)
                    acc[m][n] = fmaf(a[m], b[n], acc[m][n]);
        }
        __syncthreads();
    }
    #pragma unroll
    for (int m = 0; m < 4; m++)
        #pragma unroll
        for (int n = 0; n < 4; n++)
            g_proj[(size_t)(bm0 + ty * 4 + m) * K + tx * 4 + n] = acc[m][n] + bias[tx * 4 + n];
}

// One warp per batch element: out = dot(acc_u, acc_i)/16 + dot(Tu_u, proj_b)/max(||proj_b||,1e-12)
__global__ void k_final(const int* __restrict__ users, const int* __restrict__ items,
                        const float2* __restrict__ Tu, float* __restrict__ out) {
    int b = (blockIdx.x * blockDim.x + threadIdx.x) >> 5;
    int lane = threadIdx.x & 31;
    if (b >= BATCH) return;
    int u = users[b], it = items[b];
    const float2* acc2 = (const float2*)g_acc;
    float2 gu = acc2[(size_t)u * 32 + lane];
    float2 gi = acc2[(size_t)(NU + it) * 32 + lane];
    float d1 = gu.x * gi.x + gu.y * gi.y;
    float2 tu = Tu[(size_t)u * 32 + lane];
    const float2* pr2 = (const float2*)g_proj;
    float2 pr = pr2[(size_t)b * 32 + lane];
    float d2 = tu.x * pr.x + tu.y * pr.y;
    float ss = pr.x * pr.x + pr.y * pr.y;
    #pragma unroll
    for (int off = 16; off; off >>= 1) {
        d1 += __shfl_xor_sync(0xFFFFFFFFu, d1, off);
        d2 += __shfl_xor_sync(0xFFFFFFFFu, d2, off);
        ss += __shfl_xor_sync(0xFFFFFFFFu, ss, off);
    }
    if (lane == 0) {
        float nrm = sqrtf(ss);
        float den = fmaxf(nrm, 1e-12f);
        out[b] = d1 * (1.0f / 16.0f) + d2 / den;
    }
}

// ---------------- launch -----------------------------------------------------

extern "C" void kernel_launch(void* const* d_in, const int* in_sizes, int n_in,
                              void* d_out, int out_size) {
    const float* Gu     = (const float*)d_in[0];
    const float* Gi     = (const float*)d_in[1];
    const float* Tu     = (const float*)d_in[2];
    const float* F      = (const float*)d_in[3];
    const float* proj_w = (const float*)d_in[4];
    const float* proj_b = (const float*)d_in[5];
    const int*   ue     = (const int*)d_in[6];
    const int*   ie     = (const int*)d_in[7];
    const int*   users  = (const int*)d_in[8];
    const int*   items  = (const int*)d_in[9];
    float* out = (float*)d_out;

    k_zero_counters<<<(NN + 255) / 256, 256>>>();
    k_count<<<(NE + 255) / 256, 256>>>(ue, ie);
    k_dinv<<<(NN + 255) / 256, 256>>>();
    k_scanA<<<NBLK_SCAN, 1024>>>();
    k_scanB<<<1, 32>>>();
    k_scanC<<<(NN + 255) / 256, 256>>>();
    k_fill<<<(NE + 255) / 256, 256>>>(ue, ie);
    k_init<<<(NN * K4 + 255) / 256, 256>>>((const float4*)Gu, (const float4*)Gi);

    // 3 LightGCN layers: one half-warp per node, 16 nodes per 256-thread block
    const int PROP_BLOCKS = (NN * 16 + 255) / 256;  // 9375
    k_prop<<<PROP_BLOCKS, 256>>>(0);  // yA -> yB
    k_prop<<<PROP_BLOCKS, 256>>>(1);  // yB -> yA
    k_prop<<<PROP_BLOCKS, 256>>>(0);  // yA -> yB

    k_gemm<<<BATCH / 64, 256>>>(F, proj_w, proj_b, items);
    k_final<<<(BATCH * 32 + 255) / 256, 256>>>(users, items, (const float2*)Tu, out);
}

// round 5
// speedup vs baseline: 1.6198x; 1.1298x over previous
#include <cuda_runtime.h>
#include <cuda_bf16.h>
#include <cstdint>

// Problem constants (match reference)
#define NU    100000
#define NI    50000
#define NN    150000            // NU + NI
#define K     64
#define K4    16                // float4 per fp32 node row
#define KB4   8                 // uint4 (8 bf16) per bf16 node row
#define FEAT  1024
#define NE    3000000
#define BATCH 16384
#define NBLK_SCAN 147           // ceil(150000/1024)

// ---------------- scratch (static device allocations; no cudaMalloc) --------
__device__ int    g_deg[NN];
__device__ int    g_fill[NN];            // running fill cursor (init = rowptr)
__device__ float  g_dinv[NN];
__device__ int    g_rowptr[NN + 1];
__device__ int    g_bsum[256];
__device__ int    g_boff[256];
__device__ int    g_col[2 * NE];         // 24 MB
__device__ float4 g_acc[NN * K4];        // 38.4 MB fp32 accumulator
__device__ uint4  g_yA[NN * KB4];        // 19.2 MB bf16 rows (128 B/node)
__device__ uint4  g_yB[NN * KB4];        // 19.2 MB
__device__ float  g_proj[BATCH * K];     // 4 MB

// ---------------- kernels ---------------------------------------------------

__global__ void k_zero_counters() {
    int i = blockIdx.x * blockDim.x + threadIdx.x;
    if (i < NN) g_deg[i] = 0;
}

__global__ void k_count(const int* __restrict__ ue, const int* __restrict__ ie) {
    int e = blockIdx.x * blockDim.x + threadIdx.x;
    if (e >= NE) return;
    atomicAdd(&g_deg[ue[e]], 1);
    atomicAdd(&g_deg[NU + ie[e]], 1);
}

// Block-level exclusive scan of degrees (Hillis-Steele on 1024 elems).
// Also computes dinv (merged to save a launch).
__global__ void k_scanA() {
    __shared__ int sh[1024];
    int idx = blockIdx.x * 1024 + threadIdx.x;
    int v = (idx < NN) ? g_deg[idx] : 0;
    if (idx < NN) g_dinv[idx] = (v > 0) ? rsqrtf((float)v) : 0.0f;
    sh[threadIdx.x] = v;
    __syncthreads();
    for (int off = 1; off < 1024; off <<= 1) {
        int t = (threadIdx.x >= off) ? sh[threadIdx.x - off] : 0;
        __syncthreads();
        sh[threadIdx.x] += t;
        __syncthreads();
    }
    if (idx < NN) g_rowptr[idx] = sh[threadIdx.x] - v;  // exclusive
    if (threadIdx.x == 1023) g_bsum[blockIdx.x] = sh[1023];
}

__global__ void k_scanB() {
    if (threadIdx.x == 0) {
        int run = 0;
        for (int b = 0; b < NBLK_SCAN; b++) { int v = g_bsum[b]; g_boff[b] = run; run += v; }
        g_rowptr[NN] = run;
    }
}

__global__ void k_scanC() {
    int idx = blockIdx.x * blockDim.x + threadIdx.x;
    if (idx < NN) {
        int r = g_rowptr[idx] + g_boff[idx >> 10];
        g_rowptr[idx] = r;
        g_fill[idx] = r;   // fill cursor starts at row begin
    }
}

// Single atomic per edge endpoint: g_fill IS the running write cursor.
__global__ void k_fill(const int* __restrict__ ue, const int* __restrict__ ie) {
    int e = blockIdx.x * blockDim.x + threadIdx.x;
    if (e >= NE) return;
    int u = ue[e], it = NU + ie[e];
    int p = atomicAdd(&g_fill[u], 1);
    g_col[p] = it;
    int q = atomicAdd(&g_fill[it], 1);
    g_col[q] = u;
}

// Pack 8 fp32 (two float4) -> uint4 of bf16
__device__ __forceinline__ uint4 pack_bf16x8(float4 a, float4 b) {
    __nv_bfloat162 h0 = __float22bfloat162_rn(make_float2(a.x, a.y));
    __nv_bfloat162 h1 = __float22bfloat162_rn(make_float2(a.z, a.w));
    __nv_bfloat162 h2 = __float22bfloat162_rn(make_float2(b.x, b.y));
    __nv_bfloat162 h3 = __float22bfloat162_rn(make_float2(b.z, b.w));
    uint4 r;
    r.x = *reinterpret_cast<uint32_t*>(&h0);
    r.y = *reinterpret_cast<uint32_t*>(&h1);
    r.z = *reinterpret_cast<uint32_t*>(&h2);
    r.w = *reinterpret_cast<uint32_t*>(&h3);
    return r;
}

__device__ __forceinline__ void add_bf16x8(const uint4& v, float* s) {
    const __nv_bfloat162* h = reinterpret_cast<const __nv_bfloat162*>(&v);
    #pragma unroll
    for (int i = 0; i < 4; i++) {
        float2 f = __bfloat1622float2(h[i]);
        s[2 * i]     += f.x;
        s[2 * i + 1] += f.y;
    }
}

// acc = x0 (fp32) ; yA = bf16(dinv * x0).  One thread per uint4 (8 values).
__global__ void k_init(const float4* __restrict__ Gu, const float4* __restrict__ Gi) {
    int idx = blockIdx.x * blockDim.x + threadIdx.x;
    if (idx >= NN * KB4) return;
    int n = idx >> 3;
    int c = idx & 7;           // which group of 8 floats
    float4 x0a, x0b;
    if (n < NU) {
        x0a = Gu[(size_t)n * K4 + 2 * c];
        x0b = Gu[(size_t)n * K4 + 2 * c + 1];
    } else {
        x0a = Gi[(size_t)(n - NU) * K4 + 2 * c];
        x0b = Gi[(size_t)(n - NU) * K4 + 2 * c + 1];
    }
    g_acc[(size_t)n * K4 + 2 * c]     = x0a;
    g_acc[(size_t)n * K4 + 2 * c + 1] = x0b;
    float dv = g_dinv[n];
    float4 ya = make_float4(x0a.x * dv, x0a.y * dv, x0a.z * dv, x0a.w * dv);
    float4 yb = make_float4(x0b.x * dv, x0b.y * dv, x0b.z * dv, x0b.w * dv);
    g_yA[idx] = pack_bf16x8(ya, yb);
}

// One QUARTER-WARP (8 lanes, uint4 = 8 bf16 each) per node.
// x_next = dinv[d] * sum_{s in N(d)} y_in[s] (bf16 gather, fp32 accumulate)
// acc += x_next (fp32) ; y_out = bf16(dinv[d] * x_next)
__global__ void k_prop(int flip) {
    const uint4* __restrict__ yin = flip ? (const uint4*)g_yB : (const uint4*)g_yA;
    uint4* __restrict__ yout      = flip ? g_yA : g_yB;
    int n    = (blockIdx.x * blockDim.x + threadIdx.x) >> 3;  // node
    int lane = threadIdx.x & 7;
    if (n >= NN) return;
    int beg = g_rowptr[n], end = g_rowptr[n + 1];
    float s[8] = {0.f, 0.f, 0.f, 0.f, 0.f, 0.f, 0.f, 0.f};
    int j = beg;
    for (; j + 4 <= end; j += 4) {
        int c0 = g_col[j], c1 = g_col[j + 1], c2 = g_col[j + 2], c3 = g_col[j + 3];
        uint4 v0 = yin[(size_t)c0 * KB4 + lane];
        uint4 v1 = yin[(size_t)c1 * KB4 + lane];
        uint4 v2 = yin[(size_t)c2 * KB4 + lane];
        uint4 v3 = yin[(size_t)c3 * KB4 + lane];
        add_bf16x8(v0, s);
        add_bf16x8(v1, s);
        add_bf16x8(v2, s);
        add_bf16x8(v3, s);
    }
    for (; j < end; j++) {
        uint4 v = yin[(size_t)g_col[j] * KB4 + lane];
        add_bf16x8(v, s);
    }
    float dv = g_dinv[n];
    #pragma unroll
    for (int i = 0; i < 8; i++) s[i] *= dv;
    size_t oa = (size_t)n * K4 + 2 * lane;
    float4 a0 = g_acc[oa], a1 = g_acc[oa + 1];
    a0.x += s[0]; a0.y += s[1]; a0.z += s[2]; a0.w += s[3];
    a1.x += s[4]; a1.y += s[5]; a1.z += s[6]; a1.w += s[7];
    g_acc[oa] = a0;
    g_acc[oa + 1] = a1;
    float4 y0 = make_float4(s[0] * dv, s[1] * dv, s[2] * dv, s[3] * dv);
    float4 y1 = make_float4(s[4] * dv, s[5] * dv, s[6] * dv, s[7] * dv);
    yout[(size_t)n * KB4 + lane] = pack_bf16x8(y0, y1);
}

// proj[b][k] = sum_f F[items[b]][f] * W[k][f] + bias[k]
// 64x64 output tile per block, BK=64, 256 threads (16x16), 4x4 micro-tile.
__global__ void k_gemm(const float* __restrict__ F, const float* __restrict__ W,
                       const float* __restrict__ bias, const int* __restrict__ items) {
    __shared__ float As[64][65];
    __shared__ float Bs[64][65];
    __shared__ int   its[64];
    int bm0 = blockIdx.x * 64;
    int tid = threadIdx.x;
    int tx = tid & 15, ty = tid >> 4;
    if (tid < 64) its[tid] = items[bm0 + tid];
    __syncthreads();
    float acc[4][4] = {};
    for (int f0 = 0; f0 < FEAT; f0 += 64) {
        #pragma unroll
        for (int i = 0; i < 16; i++) {
            int idx = tid + i * 256;
            int r = idx >> 6, c = idx & 63;
            As[r][c] = F[(size_t)its[r] * FEAT + f0 + c];
            Bs[c][r] = W[(size_t)r * FEAT + f0 + c];  // Bs[f][k]
        }
        __syncthreads();
        #pragma unroll
        for (int ff = 0; ff < 64; ff++) {
            float a[4], b[4];
            #pragma unroll
            for (int m = 0; m < 4; m++) a[m] = As[ty * 4 + m][ff];
            #pragma unroll
            for (int n = 0; n < 4; n++) b[n] = Bs[ff][tx * 4 + n];
            #pragma unroll
            for (int m = 0; m < 4; m++)
                #pragma unroll
                for (int n = 0; n < 4; n++)
                    acc[m][n] = fmaf(a[m], b[n], acc[m][n]);
        }
        __syncthreads();
    }
    #pragma unroll
    for (int m = 0; m < 4; m++)
        #pragma unroll
        for (int n = 0; n < 4; n++)
            g_proj[(size_t)(bm0 + ty * 4 + m) * K + tx * 4 + n] = acc[m][n] + bias[tx * 4 + n];
}

// One warp per batch element: out = dot(acc_u, acc_i)/16 + dot(Tu_u, proj_b)/max(||proj_b||,1e-12)
__global__ void k_final(const int* __restrict__ users, const int* __restrict__ items,
                        const float2* __restrict__ Tu, float* __restrict__ out) {
    int b = (blockIdx.x * blockDim.x + threadIdx.x) >> 5;
    int lane = threadIdx.x & 31;
    if (b >= BATCH) return;
    int u = users[b], it = items[b];
    const float2* acc2 = (const float2*)g_acc;
    float2 gu = acc2[(size_t)u * 32 + lane];
    float2 gi = acc2[(size_t)(NU + it) * 32 + lane];
    float d1 = gu.x * gi.x + gu.y * gi.y;
    float2 tu = Tu[(size_t)u * 32 + lane];
    const float2* pr2 = (const float2*)g_proj;
    float2 pr = pr2[(size_t)b * 32 + lane];
    float d2 = tu.x * pr.x + tu.y * pr.y;
    float ss = pr.x * pr.x + pr.y * pr.y;
    #pragma unroll
    for (int off = 16; off; off >>= 1) {
        d1 += __shfl_xor_sync(0xFFFFFFFFu, d1, off);
        d2 += __shfl_xor_sync(0xFFFFFFFFu, d2, off);
        ss += __shfl_xor_sync(0xFFFFFFFFu, ss, off);
    }
    if (lane == 0) {
        float nrm = sqrtf(ss);
        float den = fmaxf(nrm, 1e-12f);
        out[b] = d1 * (1.0f / 16.0f) + d2 / den;
    }
}

// ---------------- launch -----------------------------------------------------

extern "C" void kernel_launch(void* const* d_in, const int* in_sizes, int n_in,
                              void* d_out, int out_size) {
    const float* Gu     = (const float*)d_in[0];
    const float* Gi     = (const float*)d_in[1];
    const float* Tu     = (const float*)d_in[2];
    const float* F      = (const float*)d_in[3];
    const float* proj_w = (const float*)d_in[4];
    const float* proj_b = (const float*)d_in[5];
    const int*   ue     = (const int*)d_in[6];
    const int*   ie     = (const int*)d_in[7];
    const int*   users  = (const int*)d_in[8];
    const int*   items  = (const int*)d_in[9];
    float* out = (float*)d_out;

    k_zero_counters<<<(NN + 255) / 256, 256>>>();
    k_count<<<(NE + 255) / 256, 256>>>(ue, ie);
    k_scanA<<<NBLK_SCAN, 1024>>>();          // scan + dinv (merged)
    k_scanB<<<1, 32>>>();
    k_scanC<<<(NN + 255) / 256, 256>>>();
    k_fill<<<(NE + 255) / 256, 256>>>(ue, ie);
    k_init<<<(NN * KB4 + 255) / 256, 256>>>((const float4*)Gu, (const float4*)Gi);

    // 3 LightGCN layers: one quarter-warp per node, 32 nodes per 256-thread block
    const int PROP_BLOCKS = (NN * 8 + 255) / 256;  // 4688
    k_prop<<<PROP_BLOCKS, 256>>>(0);  // yA -> yB
    k_prop<<<PROP_BLOCKS, 256>>>(1);  // yB -> yA
    k_prop<<<PROP_BLOCKS, 256>>>(0);  // yA -> yB

    k_gemm<<<BATCH / 64, 256>>>(F, proj_w, proj_b, items);
    k_final<<<(BATCH * 32 + 255) / 256, 256>>>(users, items, (const float2*)Tu, out);
}

// round 6
// speedup vs baseline: 1.7881x; 1.1039x over previous
#include <cuda_runtime.h>
#include <cuda_bf16.h>
#include <cstdint>

// Problem constants (match reference)
#define NU    100000
#define NI    50000
#define NN    150000            // NU + NI
#define K     64
#define K4    16                // float4 per fp32 node row
#define KB4   8                 // uint4 (8 bf16) per bf16 node row
#define FEAT  1024
#define NE    3000000
#define BATCH 16384
#define NBLK_SCAN 147           // ceil(150000/1024)

// ---------------- scratch (static device allocations; no cudaMalloc) --------
__device__ int    g_deg[NN];
__device__ int    g_fill[NN];            // running fill cursor (init = rowptr)
__device__ float  g_dinv[NN];
__device__ int    g_rowptr[NN + 1];
__device__ int    g_bsum[256];
__device__ int    g_boff[256];
__device__ int    g_mark[NN];
__device__ int    g_mlist[2 * BATCH];
__device__ int    g_nmark;
__device__ int    g_col[2 * NE];         // 24 MB
__device__ float4 g_acc[NN * K4];        // 38.4 MB: x1+x2(+x3 at marked nodes)
__device__ uint4  g_yA[NN * KB4];        // 19.2 MB bf16 rows (128 B/node)
__device__ uint4  g_yB[NN * KB4];        // 19.2 MB
__device__ float  g_proj[BATCH * K];     // 4 MB

// ---------------- kernels ---------------------------------------------------

__global__ void k_zero() {
    int i = blockIdx.x * blockDim.x + threadIdx.x;
    if (i < NN) { g_deg[i] = 0; g_mark[i] = 0; }
    if (i == 0) g_nmark = 0;
}

// Dedup batch nodes into g_mlist (order nondeterministic; per-node work is
// independent so final output is deterministic).
__global__ void k_mark(const int* __restrict__ users, const int* __restrict__ items) {
    int b = blockIdx.x * blockDim.x + threadIdx.x;
    if (b >= BATCH) return;
    int u = users[b];
    if (atomicExch(&g_mark[u], 1) == 0) { int p = atomicAdd(&g_nmark, 1); g_mlist[p] = u; }
    int it = NU + items[b];
    if (atomicExch(&g_mark[it], 1) == 0) { int p = atomicAdd(&g_nmark, 1); g_mlist[p] = it; }
}

// 4 edges per thread (int4 loads)
__global__ void k_count(const int4* __restrict__ ue4, const int4* __restrict__ ie4) {
    int e = blockIdx.x * blockDim.x + threadIdx.x;
    if (e >= NE / 4) return;
    int4 u = ue4[e], v = ie4[e];
    atomicAdd(&g_deg[u.x], 1); atomicAdd(&g_deg[u.y], 1);
    atomicAdd(&g_deg[u.z], 1); atomicAdd(&g_deg[u.w], 1);
    atomicAdd(&g_deg[NU + v.x], 1); atomicAdd(&g_deg[NU + v.y], 1);
    atomicAdd(&g_deg[NU + v.z], 1); atomicAdd(&g_deg[NU + v.w], 1);
}

// Block-level exclusive scan of degrees (Hillis-Steele on 1024 elems) + dinv.
__global__ void k_scanA() {
    __shared__ int sh[1024];
    int idx = blockIdx.x * 1024 + threadIdx.x;
    int v = (idx < NN) ? g_deg[idx] : 0;
    if (idx < NN) g_dinv[idx] = (v > 0) ? rsqrtf((float)v) : 0.0f;
    sh[threadIdx.x] = v;
    __syncthreads();
    for (int off = 1; off < 1024; off <<= 1) {
        int t = (threadIdx.x >= off) ? sh[threadIdx.x - off] : 0;
        __syncthreads();
        sh[threadIdx.x] += t;
        __syncthreads();
    }
    if (idx < NN) g_rowptr[idx] = sh[threadIdx.x] - v;  // exclusive
    if (threadIdx.x == 1023) g_bsum[blockIdx.x] = sh[1023];
}

__global__ void k_scanB() {
    if (threadIdx.x == 0) {
        int run = 0;
        for (int b = 0; b < NBLK_SCAN; b++) { int v = g_bsum[b]; g_boff[b] = run; run += v; }
        g_rowptr[NN] = run;
    }
}

__global__ void k_scanC() {
    int idx = blockIdx.x * blockDim.x + threadIdx.x;
    if (idx < NN) {
        int r = g_rowptr[idx] + g_boff[idx >> 10];
        g_rowptr[idx] = r;
        g_fill[idx] = r;   // fill cursor starts at row begin
    }
}

// Single atomic per edge endpoint; 4 edges per thread.
__global__ void k_fill(const int4* __restrict__ ue4, const int4* __restrict__ ie4) {
    int e = blockIdx.x * blockDim.x + threadIdx.x;
    if (e >= NE / 4) return;
    int4 u = ie4 ? ue4[e] : make_int4(0, 0, 0, 0);
    int4 v = ie4[e];
    int us[4] = {u.x, u.y, u.z, u.w};
    int is[4] = {NU + v.x, NU + v.y, NU + v.z, NU + v.w};
    #pragma unroll
    for (int t = 0; t < 4; t++) {
        int p = atomicAdd(&g_fill[us[t]], 1);
        g_col[p] = is[t];
        int q = atomicAdd(&g_fill[is[t]], 1);
        g_col[q] = us[t];
    }
}

// Pack 8 fp32 (two float4) -> uint4 of bf16
__device__ __forceinline__ uint4 pack_bf16x8(float4 a, float4 b) {
    __nv_bfloat162 h0 = __float22bfloat162_rn(make_float2(a.x, a.y));
    __nv_bfloat162 h1 = __float22bfloat162_rn(make_float2(a.z, a.w));
    __nv_bfloat162 h2 = __float22bfloat162_rn(make_float2(b.x, b.y));
    __nv_bfloat162 h3 = __float22bfloat162_rn(make_float2(b.z, b.w));
    uint4 r;
    r.x = *reinterpret_cast<uint32_t*>(&h0);
    r.y = *reinterpret_cast<uint32_t*>(&h1);
    r.z = *reinterpret_cast<uint32_t*>(&h2);
    r.w = *reinterpret_cast<uint32_t*>(&h3);
    return r;
}

__device__ __forceinline__ void add_bf16x8(const uint4& v, float* s) {
    const __nv_bfloat162* h = reinterpret_cast<const __nv_bfloat162*>(&v);
    #pragma unroll
    for (int i = 0; i < 4; i++) {
        float2 f = __bfloat1622float2(h[i]);
        s[2 * i]     += f.x;
        s[2 * i + 1] += f.y;
    }
}

// yA = bf16(dinv * x0).  One thread per uint4 (8 values). acc untouched.
__global__ void k_init(const float4* __restrict__ Gu, const float4* __restrict__ Gi) {
    int idx = blockIdx.x * blockDim.x + threadIdx.x;
    if (idx >= NN * KB4) return;
    int n = idx >> 3;
    int c = idx & 7;
    float4 x0a, x0b;
    if (n < NU) {
        x0a = Gu[(size_t)n * K4 + 2 * c];
        x0b = Gu[(size_t)n * K4 + 2 * c + 1];
    } else {
        x0a = Gi[(size_t)(n - NU) * K4 + 2 * c];
        x0b = Gi[(size_t)(n - NU) * K4 + 2 * c + 1];
    }
    float dv = g_dinv[n];
    float4 ya = make_float4(x0a.x * dv, x0a.y * dv, x0a.z * dv, x0a.w * dv);
    float4 yb = make_float4(x0b.x * dv, x0b.y * dv, x0b.z * dv, x0b.w * dv);
    g_yA[idx] = pack_bf16x8(ya, yb);
}

// One QUARTER-WARP (8 lanes, uint4 = 8 bf16 each) per node.
// x = dinv[d] * sum_{s in N(d)} y_in[s] (bf16 gather, fp32 accumulate)
// rmw==0: acc = x (layer 1).  rmw==1: acc += x (layer 2).
// y_out = bf16(dinv[d] * x)
__global__ void k_prop(int flip, int rmw) {
    const uint4* __restrict__ yin = flip ? (const uint4*)g_yB : (const uint4*)g_yA;
    uint4* __restrict__ yout      = flip ? g_yA : g_yB;
    int n    = (blockIdx.x * blockDim.x + threadIdx.x) >> 3;
    int lane = threadIdx.x & 7;
    if (n >= NN) return;
    int beg = g_rowptr[n], end = g_rowptr[n + 1];
    float s[8] = {0.f, 0.f, 0.f, 0.f, 0.f, 0.f, 0.f, 0.f};
    int j = beg;
    for (; j + 4 <= end; j += 4) {
        int c0 = g_col[j], c1 = g_col[j + 1], c2 = g_col[j + 2], c3 = g_col[j + 3];
        uint4 v0 = yin[(size_t)c0 * KB4 + lane];
        uint4 v1 = yin[(size_t)c1 * KB4 + lane];
        uint4 v2 = yin[(size_t)c2 * KB4 + lane];
        uint4 v3 = yin[(size_t)c3 * KB4 + lane];
        add_bf16x8(v0, s); add_bf16x8(v1, s); add_bf16x8(v2, s); add_bf16x8(v3, s);
    }
    for (; j < end; j++) {
        uint4 v = yin[(size_t)g_col[j] * KB4 + lane];
        add_bf16x8(v, s);
    }
    float dv = g_dinv[n];
    #pragma unroll
    for (int i = 0; i < 8; i++) s[i] *= dv;
    size_t oa = (size_t)n * K4 + 2 * lane;
    float4 a0 = make_float4(s[0], s[1], s[2], s[3]);
    float4 a1 = make_float4(s[4], s[5], s[6], s[7]);
    if (rmw) {
        float4 p0 = g_acc[oa], p1 = g_acc[oa + 1];
        a0.x += p0.x; a0.y += p0.y; a0.z += p0.z; a0.w += p0.w;
        a1.x += p1.x; a1.y += p1.y; a1.z += p1.z; a1.w += p1.w;
    }
    g_acc[oa] = a0;
    g_acc[oa + 1] = a1;
    float4 y0 = make_float4(s[0] * dv, s[1] * dv, s[2] * dv, s[3] * dv);
    float4 y1 = make_float4(s[4] * dv, s[5] * dv, s[6] * dv, s[7] * dv);
    yout[(size_t)n * KB4 + lane] = pack_bf16x8(y0, y1);
}

// Layer 3: only at marked (batch) nodes; reads yA (=y2); acc += x3; no y output.
__global__ void k_prop3() {
    int g    = (blockIdx.x * blockDim.x + threadIdx.x) >> 3;
    int lane = threadIdx.x & 7;
    if (g >= g_nmark) return;
    int n = g_mlist[g];
    int beg = g_rowptr[n], end = g_rowptr[n + 1];
    float s[8] = {0.f, 0.f, 0.f, 0.f, 0.f, 0.f, 0.f, 0.f};
    const uint4* __restrict__ yin = (const uint4*)g_yA;
    int j = beg;
    for (; j + 4 <= end; j += 4) {
        int c0 = g_col[j], c1 = g_col[j + 1], c2 = g_col[j + 2], c3 = g_col[j + 3];
        uint4 v0 = yin[(size_t)c0 * KB4 + lane];
        uint4 v1 = yin[(size_t)c1 * KB4 + lane];
        uint4 v2 = yin[(size_t)c2 * KB4 + lane];
        uint4 v3 = yin[(size_t)c3 * KB4 + lane];
        add_bf16x8(v0, s); add_bf16x8(v1, s); add_bf16x8(v2, s); add_bf16x8(v3, s);
    }
    for (; j < end; j++) {
        uint4 v = yin[(size_t)g_col[j] * KB4 + lane];
        add_bf16x8(v, s);
    }
    float dv = g_dinv[n];
    size_t oa = (size_t)n * K4 + 2 * lane;
    float4 a0 = g_acc[oa], a1 = g_acc[oa + 1];
    a0.x += s[0] * dv; a0.y += s[1] * dv; a0.z += s[2] * dv; a0.w += s[3] * dv;
    a1.x += s[4] * dv; a1.y += s[5] * dv; a1.z += s[6] * dv; a1.w += s[7] * dv;
    g_acc[oa] = a0;
    g_acc[oa + 1] = a1;
}

// proj[b][k] = sum_f F[items[b]][f] * W[k][f] + bias[k]
__global__ void k_gemm(const float* __restrict__ F, const float* __restrict__ W,
                       const float* __restrict__ bias, const int* __restrict__ items) {
    __shared__ float As[64][65];
    __shared__ float Bs[64][65];
    __shared__ int   its[64];
    int bm0 = blockIdx.x * 64;
    int tid = threadIdx.x;
    int tx = tid & 15, ty = tid >> 4;
    if (tid < 64) its[tid] = items[bm0 + tid];
    __syncthreads();
    float acc[4][4] = {};
    for (int f0 = 0; f0 < FEAT; f0 += 64) {
        #pragma unroll
        for (int i = 0; i < 16; i++) {
            int idx = tid + i * 256;
            int r = idx >> 6, c = idx & 63;
            As[r][c] = F[(size_t)its[r] * FEAT + f0 + c];
            Bs[c][r] = W[(size_t)r * FEAT + f0 + c];
        }
        __syncthreads();
        #pragma unroll
        for (int ff = 0; ff < 64; ff++) {
            float a[4], b[4];
            #pragma unroll
            for (int m = 0; m < 4; m++) a[m] = As[ty * 4 + m][ff];
            #pragma unroll
            for (int n = 0; n < 4; n++) b[n] = Bs[ff][tx * 4 + n];
            #pragma unroll
            for (int m = 0; m < 4; m++)
                #pragma unroll
                for (int n = 0; n < 4; n++)
                    acc[m][n] = fmaf(a[m], b[n], acc[m][n]);
        }
        __syncthreads();
    }
    #pragma unroll
    for (int m = 0; m < 4; m++)
        #pragma unroll
        for (int n = 0; n < 4; n++)
            g_proj[(size_t)(bm0 + ty * 4 + m) * K + tx * 4 + n] = acc[m][n] + bias[tx * 4 + n];
}

// One warp per batch element. gamma = (x0 + acc)/4.
__global__ void k_final(const int* __restrict__ users, const int* __restrict__ items,
                        const float2* __restrict__ Gu, const float2* __restrict__ Gi,
                        const float2* __restrict__ Tu, float* __restrict__ out) {
    int b = (blockIdx.x * blockDim.x + threadIdx.x) >> 5;
    int lane = threadIdx.x & 31;
    if (b >= BATCH) return;
    int u = users[b], it = items[b];
    const float2* acc2 = (const float2*)g_acc;
    float2 au = acc2[(size_t)u * 32 + lane];
    float2 x0u = Gu[(size_t)u * 32 + lane];
    float2 gu = make_float2(x0u.x + au.x, x0u.y + au.y);
    float2 ai = acc2[(size_t)(NU + it) * 32 + lane];
    float2 x0i = Gi[(size_t)it * 32 + lane];
    float2 gi = make_float2(x0i.x + ai.x, x0i.y + ai.y);
    float d1 = gu.x * gi.x + gu.y * gi.y;
    float2 tu = Tu[(size_t)u * 32 + lane];
    const float2* pr2 = (const float2*)g_proj;
    float2 pr = pr2[(size_t)b * 32 + lane];
    float d2 = tu.x * pr.x + tu.y * pr.y;
    float ss = pr.x * pr.x + pr.y * pr.y;
    #pragma unroll
    for (int off = 16; off; off >>= 1) {
        d1 += __shfl_xor_sync(0xFFFFFFFFu, d1, off);
        d2 += __shfl_xor_sync(0xFFFFFFFFu, d2, off);
        ss += __shfl_xor_sync(0xFFFFFFFFu, ss, off);
    }
    if (lane == 0) {
        float nrm = sqrtf(ss);
        float den = fmaxf(nrm, 1e-12f);
        out[b] = d1 * (1.0f / 16.0f) + d2 / den;
    }
}

// ---------------- launch -----------------------------------------------------

extern "C" void kernel_launch(void* const* d_in, const int* in_sizes, int n_in,
                              void* d_out, int out_size) {
    const float* Gu     = (const float*)d_in[0];
    const float* Gi     = (const float*)d_in[1];
    const float* Tu     = (const float*)d_in[2];
    const float* F      = (const float*)d_in[3];
    const float* proj_w = (const float*)d_in[4];
    const float* proj_b = (const float*)d_in[5];
    const int*   ue     = (const int*)d_in[6];
    const int*   ie     = (const int*)d_in[7];
    const int*   users  = (const int*)d_in[8];
    const int*   items  = (const int*)d_in[9];
    float* out = (float*)d_out;

    k_zero<<<(NN + 255) / 256, 256>>>();                              // 1
    k_mark<<<(BATCH + 255) / 256, 256>>>(users, items);               // 2
    k_gemm<<<BATCH / 64, 256>>>(F, proj_w, proj_b, items);            // 3
    k_count<<<(NE / 4 + 255) / 256, 256>>>((const int4*)ue, (const int4*)ie);  // 4 (ncu lands here)
    k_scanA<<<NBLK_SCAN, 1024>>>();                                   // 5
    k_scanB<<<1, 32>>>();                                             // 6
    k_scanC<<<(NN + 255) / 256, 256>>>();                             // 7
    k_fill<<<(NE / 4 + 255) / 256, 256>>>((const int4*)ue, (const int4*)ie);   // 8
    k_init<<<(NN * KB4 + 255) / 256, 256>>>((const float4*)Gu, (const float4*)Gi); // 9

    const int PROP_BLOCKS = (NN * 8 + 255) / 256;  // 4688
    k_prop<<<PROP_BLOCKS, 256>>>(0, 0);   // layer1: yA -> yB, acc = x1
    k_prop<<<PROP_BLOCKS, 256>>>(1, 1);   // layer2: yB -> yA, acc += x2
    k_prop3<<<(2 * BATCH * 8 + 255) / 256, 256>>>();  // layer3: marked only

    k_final<<<(BATCH * 32 + 255) / 256, 256>>>(users, items,
                                               (const float2*)Gu, (const float2*)Gi,
                                               (const float2*)Tu, out);
}

// round 8
// speedup vs baseline: 2.3491x; 1.3137x over previous
#include <cuda_runtime.h>
#include <cuda_bf16.h>
#include <cstdint>

// Problem constants (match reference)
#define NU    100000
#define NI    50000
#define NN    150000            // NU + NI
#define K     64
#define K4    16                // float4 per fp32 node row
#define KB4   8                 // uint4 (8 bf16) per bf16 node row
#define FEAT  1024
#define NE    3000000
#define BATCH 16384
#define NBLK_SCAN 147           // ceil(150000/1024)

// ---------------- scratch (static device allocations; no cudaMalloc) --------
__device__ int    g_deg[NN];
__device__ int    g_fill[NN];            // running fill cursor (init = rowptr)
__device__ float  g_dinv[NN];
__device__ int    g_rowptr[NN + 1];
__device__ int    g_bsum[256];
__device__ int    g_boff[256];
__device__ int    g_mark[NN];
__device__ int    g_mlist[2 * BATCH];
__device__ int    g_nmark;
__device__ int    g_col[2 * NE];         // 24 MB
__device__ float4 g_acc[NN * K4];        // 38.4 MB (only marked rows are valid)
__device__ uint4  g_yA[NN * KB4];        // 19.2 MB bf16 rows (128 B/node)
__device__ uint4  g_yB[NN * KB4];        // 19.2 MB
__device__ float  g_proj[BATCH * K];     // 4 MB

// ---------------- kernels ---------------------------------------------------

__global__ void k_zero() {
    int i = blockIdx.x * blockDim.x + threadIdx.x;
    if (i < NN) { g_deg[i] = 0; g_mark[i] = 0; }
    if (i == 0) g_nmark = 0;
}

// Dedup batch nodes into g_mlist (order nondeterministic; per-node work is
// independent so the final output is deterministic).
__global__ void k_mark(const int* __restrict__ users, const int* __restrict__ items) {
    int b = blockIdx.x * blockDim.x + threadIdx.x;
    if (b >= BATCH) return;
    int u = users[b];
    if (atomicExch(&g_mark[u], 1) == 0) { int p = atomicAdd(&g_nmark, 1); g_mlist[p] = u; }
    int it = NU + items[b];
    if (atomicExch(&g_mark[it], 1) == 0) { int p = atomicAdd(&g_nmark, 1); g_mlist[p] = it; }
}

// 4 edges per thread (int4 loads)
__global__ void k_count(const int4* __restrict__ ue4, const int4* __restrict__ ie4) {
    int e = blockIdx.x * blockDim.x + threadIdx.x;
    if (e >= NE / 4) return;
    int4 u = ue4[e], v = ie4[e];
    atomicAdd(&g_deg[u.x], 1); atomicAdd(&g_deg[u.y], 1);
    atomicAdd(&g_deg[u.z], 1); atomicAdd(&g_deg[u.w], 1);
    atomicAdd(&g_deg[NU + v.x], 1); atomicAdd(&g_deg[NU + v.y], 1);
    atomicAdd(&g_deg[NU + v.z], 1); atomicAdd(&g_deg[NU + v.w], 1);
}

// Block-level exclusive scan of degrees (Hillis-Steele on 1024 elems) + dinv.
__global__ void k_scanA() {
    __shared__ int sh[1024];
    int idx = blockIdx.x * 1024 + threadIdx.x;
    int v = (idx < NN) ? g_deg[idx] : 0;
    if (idx < NN) g_dinv[idx] = (v > 0) ? rsqrtf((float)v) : 0.0f;
    sh[threadIdx.x] = v;
    __syncthreads();
    for (int off = 1; off < 1024; off <<= 1) {
        int t = (threadIdx.x >= off) ? sh[threadIdx.x - off] : 0;
        __syncthreads();
        sh[threadIdx.x] += t;
        __syncthreads();
    }
    if (idx < NN) g_rowptr[idx] = sh[threadIdx.x] - v;  // exclusive
    if (threadIdx.x == 1023) g_bsum[blockIdx.x] = sh[1023];
}

// Parallel scan of the 147 block sums (one 256-thread block).
__global__ void k_scanB() {
    __shared__ int sh[256];
    int t = threadIdx.x;
    int v = (t < NBLK_SCAN) ? g_bsum[t] : 0;
    sh[t] = v;
    __syncthreads();
    for (int off = 1; off < 256; off <<= 1) {
        int x = (t >= off) ? sh[t - off] : 0;
        __syncthreads();
        sh[t] += x;
        __syncthreads();
    }
    if (t < NBLK_SCAN) g_boff[t] = sh[t] - v;  // exclusive
    if (t == 255) g_rowptr[NN] = sh[255];
}

__global__ void k_scanC() {
    int idx = blockIdx.x * blockDim.x + threadIdx.x;
    if (idx < NN) {
        int r = g_rowptr[idx] + g_boff[idx >> 10];
        g_rowptr[idx] = r;
        g_fill[idx] = r;   // fill cursor starts at row begin
    }
}

// Single atomic per edge endpoint; 4 edges per thread.
__global__ void k_fill(const int4* __restrict__ ue4, const int4* __restrict__ ie4) {
    int e = blockIdx.x * blockDim.x + threadIdx.x;
    if (e >= NE / 4) return;
    int4 u = ue4[e];
    int4 v = ie4[e];
    int us[4] = {u.x, u.y, u.z, u.w};
    int is[4] = {NU + v.x, NU + v.y, NU + v.z, NU + v.w};
    #pragma unroll
    for (int t = 0; t < 4; t++) {
        int p = atomicAdd(&g_fill[us[t]], 1);
        g_col[p] = is[t];
        int q = atomicAdd(&g_fill[is[t]], 1);
        g_col[q] = us[t];
    }
}

// Pack 8 fp32 (two float4) -> uint4 of bf16
__device__ __forceinline__ uint4 pack_bf16x8(float4 a, float4 b) {
    __nv_bfloat162 h0 = __float22bfloat162_rn(make_float2(a.x, a.y));
    __nv_bfloat162 h1 = __float22bfloat162_rn(make_float2(a.z, a.w));
    __nv_bfloat162 h2 = __float22bfloat162_rn(make_float2(b.x, b.y));
    __nv_bfloat162 h3 = __float22bfloat162_rn(make_float2(b.z, b.w));
    uint4 r;
    r.x = *reinterpret_cast<uint32_t*>(&h0);
    r.y = *reinterpret_cast<uint32_t*>(&h1);
    r.z = *reinterpret_cast<uint32_t*>(&h2);
    r.w = *reinterpret_cast<uint32_t*>(&h3);
    return r;
}

__device__ __forceinline__ void add_bf16x8(const uint4& v, float* s) {
    const __nv_bfloat162* h = reinterpret_cast<const __nv_bfloat162*>(&v);
    #pragma unroll
    for (int i = 0; i < 4; i++) {
        float2 f = __bfloat1622float2(h[i]);
        s[2 * i]     += f.x;
        s[2 * i + 1] += f.y;
    }
}

// yA = bf16(dinv * x0).  One thread per uint4 (8 values).
__global__ void k_init(const float4* __restrict__ Gu, const float4* __restrict__ Gi) {
    int idx = blockIdx.x * blockDim.x + threadIdx.x;
    if (idx >= NN * KB4) return;
    int n = idx >> 3;
    int c = idx & 7;
    float4 x0a, x0b;
    if (n < NU) {
        x0a = Gu[(size_t)n * K4 + 2 * c];
        x0b = Gu[(size_t)n * K4 + 2 * c + 1];
    } else {
        x0a = Gi[(size_t)(n - NU) * K4 + 2 * c];
        x0b = Gi[(size_t)(n - NU) * K4 + 2 * c + 1];
    }
    float dv = g_dinv[n];
    float4 ya = make_float4(x0a.x * dv, x0a.y * dv, x0a.z * dv, x0a.w * dv);
    float4 yb = make_float4(x0b.x * dv, x0b.y * dv, x0b.z * dv, x0b.w * dv);
    g_yA[idx] = pack_bf16x8(ya, yb);
}

// One QUARTER-WARP (8 lanes, uint4 = 8 bf16 each) per node.
// x = dinv[d] * sum_{s in N(d)} y_in[s] (bf16 gather, fp32 accumulate)
// acc is only written at MARKED nodes (rmw==0: acc = x; rmw==1: acc += x).
// y_out = bf16(dinv[d] * x)
__global__ void k_prop(int flip, int rmw) {
    const uint4* __restrict__ yin = flip ? (const uint4*)g_yB : (const uint4*)g_yA;
    uint4* __restrict__ yout      = flip ? g_yA : g_yB;
    int n    = (blockIdx.x * blockDim.x + threadIdx.x) >> 3;
    int lane = threadIdx.x & 7;
    if (n >= NN) return;
    int beg = g_rowptr[n], end = g_rowptr[n + 1];
    float s[8] = {0.f, 0.f, 0.f, 0.f, 0.f, 0.f, 0.f, 0.f};
    int j = beg;
    for (; j + 8 <= end; j += 8) {
        uint4 v[8];
        #pragma unroll
        for (int t = 0; t < 8; t++) {
            int c = g_col[j + t];
            v[t] = yin[(size_t)c * KB4 + lane];
        }
        #pragma unroll
        for (int t = 0; t < 8; t++) add_bf16x8(v[t], s);
    }
    for (; j < end; j++) {
        uint4 v = yin[(size_t)g_col[j] * KB4 + lane];
        add_bf16x8(v, s);
    }
    float dv = g_dinv[n];
    #pragma unroll
    for (int i = 0; i < 8; i++) s[i] *= dv;
    if (g_mark[n]) {
        size_t oa = (size_t)n * K4 + 2 * lane;
        float4 a0 = make_float4(s[0], s[1], s[2], s[3]);
        float4 a1 = make_float4(s[4], s[5], s[6], s[7]);
        if (rmw) {
            float4 p0 = g_acc[oa], p1 = g_acc[oa + 1];
            a0.x += p0.x; a0.y += p0.y; a0.z += p0.z; a0.w += p0.w;
            a1.x += p1.x; a1.y += p1.y; a1.z += p1.z; a1.w += p1.w;
        }
        g_acc[oa] = a0;
        g_acc[oa + 1] = a1;
    }
    float4 y0 = make_float4(s[0] * dv, s[1] * dv, s[2] * dv, s[3] * dv);
    float4 y1 = make_float4(s[4] * dv, s[5] * dv, s[6] * dv, s[7] * dv);
    yout[(size_t)n * KB4 + lane] = pack_bf16x8(y0, y1);
}

// Layer 3: only at marked (batch) nodes; reads yA (=y2); acc += x3; no y output.
__global__ void k_prop3() {
    int g    = (blockIdx.x * blockDim.x + threadIdx.x) >> 3;
    int lane = threadIdx.x & 7;
    if (g >= g_nmark) return;
    int n = g_mlist[g];
    int beg = g_rowptr[n], end = g_rowptr[n + 1];
    float s[8] = {0.f, 0.f, 0.f, 0.f, 0.f, 0.f, 0.f, 0.f};
    const uint4* __restrict__ yin = (const uint4*)g_yA;
    int j = beg;
    for (; j + 8 <= end; j += 8) {
        uint4 v[8];
        #pragma unroll
        for (int t = 0; t < 8; t++) {
            int c = g_col[j + t];
            v[t] = yin[(size_t)c * KB4 + lane];
        }
        #pragma unroll
        for (int t = 0; t < 8; t++) add_bf16x8(v[t], s);
    }
    for (; j < end; j++) {
        uint4 v = yin[(size_t)g_col[j] * KB4 + lane];
        add_bf16x8(v, s);
    }
    float dv = g_dinv[n];
    size_t oa = (size_t)n * K4 + 2 * lane;
    float4 a0 = g_acc[oa], a1 = g_acc[oa + 1];
    a0.x += s[0] * dv; a0.y += s[1] * dv; a0.z += s[2] * dv; a0.w += s[3] * dv;
    a1.x += s[4] * dv; a1.y += s[5] * dv; a1.z += s[6] * dv; a1.w += s[7] * dv;
    g_acc[oa] = a0;
    g_acc[oa + 1] = a1;
}

// proj[b][k] = sum_f F[items[b]][f] * W[k][f] + bias[k]
__global__ void k_gemm(const float* __restrict__ F, const float* __restrict__ W,
                       const float* __restrict__ bias, const int* __restrict__ items) {
    __shared__ float As[64][65];
    __shared__ float Bs[64][65];
    __shared__ int   its[64];
    int bm0 = blockIdx.x * 64;
    int tid = threadIdx.x;
    int tx = tid & 15, ty = tid >> 4;
    if (tid < 64) its[tid] = items[bm0 + tid];
    __syncthreads();
    float acc[4][4] = {};
    for (int f0 = 0; f0 < FEAT; f0 += 64) {
        #pragma unroll
        for (int i = 0; i < 16; i++) {
            int idx = tid + i * 256;
            int r = idx >> 6, c = idx & 63;
            As[r][c] = F[(size_t)its[r] * FEAT + f0 + c];
            Bs[c][r] = W[(size_t)r * FEAT + f0 + c];
        }
        __syncthreads();
        #pragma unroll
        for (int ff = 0; ff < 64; ff++) {
            float a[4], b[4];
            #pragma unroll
            for (int m = 0; m < 4; m++) a[m] = As[ty * 4 + m][ff];
            #pragma unroll
            for (int n = 0; n < 4; n++) b[n] = Bs[ff][tx * 4 + n];
            #pragma unroll
            for (int m = 0; m < 4; m++)
                #pragma unroll
                for (int n = 0; n < 4; n++)
                    acc[m][n] = fmaf(a[m], b[n], acc[m][n]);
        }
        __syncthreads();
    }
    #pragma unroll
    for (int m = 0; m < 4; m++)
        #pragma unroll
        for (int n = 0; n < 4; n++)
            g_proj[(size_t)(bm0 + ty * 4 + m) * K + tx * 4 + n] = acc[m][n] + bias[tx * 4 + n];
}

// One warp per batch element. gamma = (x0 + acc)/4.
__global__ void k_final(const int* __restrict__ users, const int* __restrict__ items,
                        const float2* __restrict__ Gu, const float2* __restrict__ Gi,
                        const float2* __restrict__ Tu, float* __restrict__ out) {
    int b = (blockIdx.x * blockDim.x + threadIdx.x) >> 5;
    int lane = threadIdx.x & 31;
    if (b >= BATCH) return;
    int u = users[b], it = items[b];
    const float2* acc2 = (const float2*)g_acc;
    float2 au = acc2[(size_t)u * 32 + lane];
    float2 x0u = Gu[(size_t)u * 32 + lane];
    float2 gu = make_float2(x0u.x + au.x, x0u.y + au.y);
    float2 ai = acc2[(size_t)(NU + it) * 32 + lane];
    float2 x0i = Gi[(size_t)it * 32 + lane];
    float2 gi = make_float2(x0i.x + ai.x, x0i.y + ai.y);
    float d1 = gu.x * gi.x + gu.y * gi.y;
    float2 tu = Tu[(size_t)u * 32 + lane];
    const float2* pr2 = (const float2*)g_proj;
    float2 pr = pr2[(size_t)b * 32 + lane];
    float d2 = tu.x * pr.x + tu.y * pr.y;
    float ss = pr.x * pr.x + pr.y * pr.y;
    #pragma unroll
    for (int off = 16; off; off >>= 1) {
        d1 += __shfl_xor_sync(0xFFFFFFFFu, d1, off);
        d2 += __shfl_xor_sync(0xFFFFFFFFu, d2, off);
        ss += __shfl_xor_sync(0xFFFFFFFFu, ss, off);
    }
    if (lane == 0) {
        float nrm = sqrtf(ss);
        float den = fmaxf(nrm, 1e-12f);
        out[b] = d1 * (1.0f / 16.0f) + d2 / den;
    }
}

// ---------------- launch -----------------------------------------------------
// Fork/join on side streams (gemm depends only on inputs; init only on scanA).
// Streams/events are created ONCE on the first (uncaptured correctness) call and
// NEVER destroyed: destroying capture-participating streams/events while the
// main stream is still capturing invalidates the capture (suspected cause of
// the R7 failure). Identical launch DAG every call -> deterministic graph.

extern "C" void kernel_launch(void* const* d_in, const int* in_sizes, int n_in,
                              void* d_out, int out_size) {
    const float* Gu     = (const float*)d_in[0];
    const float* Gi     = (const float*)d_in[1];
    const float* Tu     = (const float*)d_in[2];
    const float* F      = (const float*)d_in[3];
    const float* proj_w = (const float*)d_in[4];
    const float* proj_b = (const float*)d_in[5];
    const int*   ue     = (const int*)d_in[6];
    const int*   ie     = (const int*)d_in[7];
    const int*   users  = (const int*)d_in[8];
    const int*   items  = (const int*)d_in[9];
    float* out = (float*)d_out;

    static cudaStream_t sG = nullptr, sI = nullptr;
    static cudaEvent_t eStart = nullptr, eScanA = nullptr, eGemm = nullptr, eInit = nullptr;
    if (!sG) {
        cudaStreamCreateWithFlags(&sG, cudaStreamNonBlocking);
        cudaStreamCreateWithFlags(&sI, cudaStreamNonBlocking);
        cudaEventCreateWithFlags(&eStart, cudaEventDisableTiming);
        cudaEventCreateWithFlags(&eScanA, cudaEventDisableTiming);
        cudaEventCreateWithFlags(&eGemm,  cudaEventDisableTiming);
        cudaEventCreateWithFlags(&eInit,  cudaEventDisableTiming);
    }

    // Fork gemm stream at entry
    cudaEventRecord(eStart, 0);
    cudaStreamWaitEvent(sG, eStart, 0);
    k_gemm<<<BATCH / 64, 256, 0, sG>>>(F, proj_w, proj_b, items);
    cudaEventRecord(eGemm, sG);

    // Main chain: zero -> mark -> count -> scanA
    k_zero<<<(NN + 255) / 256, 256>>>();
    k_mark<<<(BATCH + 255) / 256, 256>>>(users, items);
    k_count<<<(NE / 4 + 255) / 256, 256>>>((const int4*)ue, (const int4*)ie);
    k_scanA<<<NBLK_SCAN, 1024>>>();
    cudaEventRecord(eScanA, 0);

    // Fork init (needs dinv only) concurrent with scanB/scanC/fill
    cudaStreamWaitEvent(sI, eScanA, 0);
    k_init<<<(NN * KB4 + 255) / 256, 256, 0, sI>>>((const float4*)Gu, (const float4*)Gi);
    cudaEventRecord(eInit, sI);

    k_scanB<<<1, 256>>>();
    k_scanC<<<(NN + 255) / 256, 256>>>();
    k_fill<<<(NE / 4 + 255) / 256, 256>>>((const int4*)ue, (const int4*)ie);

    // Join init before propagation
    cudaStreamWaitEvent(0, eInit, 0);
    const int PROP_BLOCKS = (NN * 8 + 255) / 256;  // 4688
    k_prop<<<PROP_BLOCKS, 256>>>(0, 0);   // layer1: yA -> yB, acc = x1 (marked)
    k_prop<<<PROP_BLOCKS, 256>>>(1, 1);   // layer2: yB -> yA, acc += x2 (marked)
    k_prop3<<<(2 * BATCH * 8 + 255) / 256, 256>>>();  // layer3: marked only

    // Join gemm before final
    cudaStreamWaitEvent(0, eGemm, 0);
    k_final<<<(BATCH * 32 + 255) / 256, 256>>>(users, items,
                                               (const float2*)Gu, (const float2*)Gi,
                                               (const float2*)Tu, out);
}